// round 6
// baseline (speedup 1.0000x reference)
#include <cuda_runtime.h>
#include <cuda_bf16.h>

// Problem constants
#define S 8192
#define E 64
#define D 4096
#define CAP 128
#define SE 524288          // S*E
#define SEC 67108864LL     // S*E*CAP

#define GEMM_BLOCKS 512
#define K3_SMEM_CAP 4096   // smem compaction capacity per expert

// ---------------- device scratch (no allocations allowed) ----------------
__device__ float g_part[4 * SE];        // split-K partial logits (8 MB)
__device__ int   g_assign[S];
__device__ float g_topgate[S];
__device__ float g_cspart[1024 * 64];   // per-block gate column sums
__device__ int   g_counts[64];

// ---------------- f32x2 helpers ----------------
__device__ __forceinline__ unsigned long long packdup(float a) {
    unsigned long long r;
    asm("mov.b64 %0, {%1, %2};" : "=l"(r) : "f"(a), "f"(a));
    return r;
}
__device__ __forceinline__ void fma2(unsigned long long& d, unsigned long long a, unsigned long long b) {
    asm("fma.rn.f32x2 %0, %1, %2, %0;" : "+l"(d) : "l"(a), "l"(b));
}
__device__ __forceinline__ void unpack2(unsigned long long v, float& lo, float& hi) {
    asm("mov.b64 {%0, %1}, %2;" : "=f"(lo), "=f"(hi) : "l"(v));
}

// ==========================================================================
// K1 (hybrid): every block = split-K GEMM tile (64 tok x 64 exp x K=1024)
//              PLUS 1/512 of the 536 MB output zero-fill, interleaved into
//              the k-mainloop so store drain overlaps FMA on EVERY SM.
// ==========================================================================
__global__ __launch_bounds__(128, 4) void k1_fused(const float* __restrict__ x,
                                                   const float* __restrict__ w,
                                                   float* __restrict__ out,
                                                   long long out_n) {
    const int tid = threadIdx.x;
    const int kp = blockIdx.x & 3;
    const int tb = blockIdx.x >> 2;
    const int t0 = tb * 64;
    const int kbase = kp * 1024;

    if (blockIdx.x == 0 && tid == 0) {
        for (int e = 0; e < 64; e++) g_counts[e] = 0;
    }

    // zero-fill addressing: thread covers {zbase + j*65536 : j in [0,512)}
    float4* const outz = reinterpret_cast<float4*>(out) + ((long long)blockIdx.x * 128 + tid);
    const float4 zf4 = make_float4(0.f, 0.f, 0.f, 0.f);

    __shared__ __align__(16) float xs[2][32][66];
    __shared__ __align__(16) float ws[2][32][65];

    const int tm = tid & 7;    // token group
    const int tn = tid >> 3;   // expert group

    // preload k-step 0
    {
#pragma unroll
        for (int r = 0; r < 4; r++) {
            int idx = tid + r * 128;
            int row = idx >> 3;
            int kq  = (idx & 7) << 2;
            float4 xv = *reinterpret_cast<const float4*>(&x[(size_t)(t0 + row) * D + kbase + kq]);
            xs[0][kq + 0][row] = xv.x; xs[0][kq + 1][row] = xv.y;
            xs[0][kq + 2][row] = xv.z; xs[0][kq + 3][row] = xv.w;
            float4 wv = *reinterpret_cast<const float4*>(&w[(size_t)row * D + kbase + kq]);
            ws[0][kq + 0][row] = wv.x; ws[0][kq + 1][row] = wv.y;
            ws[0][kq + 2][row] = wv.z; ws[0][kq + 3][row] = wv.w;
        }
    }
    __syncthreads();

    unsigned long long acc[4][4];
#pragma unroll
    for (int i = 0; i < 4; i++)
#pragma unroll
        for (int j = 0; j < 4; j++) acc[i][j] = 0ULL;

    const int NKB = 1024 / 32;  // 32
    for (int kb = 0; kb < NKB; kb++) {
        const int buf = kb & 1;
        float4 px[4], pw[4];
        if (kb + 1 < NKB) {
            const int k0 = kbase + (kb + 1) * 32;
#pragma unroll
            for (int r = 0; r < 4; r++) {
                int idx = tid + r * 128;
                int row = idx >> 3;
                int kq  = (idx & 7) << 2;
                px[r] = *reinterpret_cast<const float4*>(&x[(size_t)(t0 + row) * D + k0 + kq]);
                pw[r] = *reinterpret_cast<const float4*>(&w[(size_t)row * D + k0 + kq]);
            }
        }

        // ---- interleaved zero-fill: 16 streaming stores per k-step ----
        // indices kb*16 .. kb*16+15, stride 65536 float4s; all < 33554432 <= nv4
        {
            float4* p = outz + (long long)(kb * 16) * 65536LL;
#pragma unroll
            for (int r = 0; r < 16; r++) {
                __stcs(p, zf4);
                p += 65536LL;
            }
        }

#pragma unroll
        for (int kk = 0; kk < 32; kk++) {
            unsigned long long xp[4];
#pragma unroll
            for (int i = 0; i < 4; i++)
                xp[i] = *reinterpret_cast<const unsigned long long*>(&xs[buf][kk][8 * tm + 2 * i]);
#pragma unroll
            for (int j = 0; j < 4; j++) {
                unsigned long long wp = packdup(ws[buf][kk][4 * tn + j]);
#pragma unroll
                for (int i = 0; i < 4; i++) fma2(acc[i][j], xp[i], wp);
            }
        }
        if (kb + 1 < NKB) {
            const int nb = buf ^ 1;
#pragma unroll
            for (int r = 0; r < 4; r++) {
                int idx = tid + r * 128;
                int row = idx >> 3;
                int kq  = (idx & 7) << 2;
                xs[nb][kq + 0][row] = px[r].x; xs[nb][kq + 1][row] = px[r].y;
                xs[nb][kq + 2][row] = px[r].z; xs[nb][kq + 3][row] = px[r].w;
                ws[nb][kq + 0][row] = pw[r].x; ws[nb][kq + 1][row] = pw[r].y;
                ws[nb][kq + 2][row] = pw[r].z; ws[nb][kq + 3][row] = pw[r].w;
            }
        }
        __syncthreads();
    }

    // zero-fill remainder: nv4 may exceed 512*65536 = 33554432 by a few
    {
        const long long nv4 = out_n >> 2;
        if (blockIdx.x == 0) {
            for (long long i = 33554432LL + tid; i < nv4; i += 128)
                __stcs(reinterpret_cast<float4*>(out) + i, zf4);
            if (tid == 0) {   // scalar tail elements (land in exp_counts, also rewritten by k3)
                for (long long i = (nv4 << 2); i < out_n; i++) out[i] = 0.f;
            }
        }
    }

    // write partials
    float* part = &g_part[(size_t)kp * SE];
#pragma unroll
    for (int i = 0; i < 4; i++) {
#pragma unroll
        for (int j = 0; j < 4; j++) {
            float lo, hi;
            unpack2(acc[i][j], lo, hi);
            int t = t0 + 8 * tm + 2 * i;
            int e = 4 * tn + j;
            part[(size_t)t * E + e]       = lo;
            part[(size_t)(t + 1) * E + e] = hi;
        }
    }
}

// ==========================================================================
// K2: sum split-K partials, softmax + argmax per token, per-block column
//     sums + per-expert counts. grid 1024 x 256 (one warp per token).
// ==========================================================================
__global__ __launch_bounds__(256) void k2_gate() {
    __shared__ float cs[64];
    __shared__ int   cnt[64];
    const int tid = threadIdx.x;
    if (tid < 64) { cs[tid] = 0.f; cnt[tid] = 0; }
    __syncthreads();

    const int wid = tid >> 5, lane = tid & 31;
    const int t = blockIdx.x * 8 + wid;
    const size_t b = (size_t)t * E;

    float l0 = 0.f, l1 = 0.f;
#pragma unroll
    for (int p = 0; p < 4; p++) {
        l0 += g_part[(size_t)p * SE + b + lane];
        l1 += g_part[(size_t)p * SE + b + 32 + lane];
    }

    float bv; int bi;
    if (l0 >= l1) { bv = l0; bi = lane; } else { bv = l1; bi = lane + 32; }
#pragma unroll
    for (int o = 16; o; o >>= 1) {
        float ov = __shfl_xor_sync(0xFFFFFFFFu, bv, o);
        int   oi = __shfl_xor_sync(0xFFFFFFFFu, bi, o);
        if (ov > bv || (ov == bv && oi < bi)) { bv = ov; bi = oi; }
    }
    float e0 = __expf(l0 - bv), e1 = __expf(l1 - bv);
    float z = e0 + e1;
#pragma unroll
    for (int o = 16; o; o >>= 1) z += __shfl_xor_sync(0xFFFFFFFFu, z, o);
    float inv = 1.0f / z;

    atomicAdd(&cs[lane],      e0 * inv);
    atomicAdd(&cs[lane + 32], e1 * inv);
    if (lane == 0) {
        g_assign[t]  = bi;
        g_topgate[t] = inv;
        atomicAdd(&cnt[bi], 1);
    }
    __syncthreads();
    if (tid < 64) {
        g_cspart[blockIdx.x * 64 + tid] = cs[tid];
        atomicAdd(&g_counts[tid], cnt[tid]);
    }
}

// ==========================================================================
// K3: blocks 0..63: per-expert top-CAP selection (smem compaction + bit
//     threshold search + exact tie-break + cumsum slots), writes output
//     nonzeros DIRECTLY (zero-fill completed in k1).
//     block 64: exp_counts + l_aux into output.
// ==========================================================================
__global__ __launch_bounds__(256) void k3_select(const float* __restrict__ noise,
                                                 float* __restrict__ out) {
    const int tid = threadIdx.x;
    const int lane = tid & 31, wid = tid >> 5;

    __shared__ unsigned bits[K3_SMEM_CAP];        // 16 KB
    __shared__ unsigned short tok[K3_SMEM_CAP];   // 8 KB
    __shared__ int red[8];
    __shared__ int weq[8], wkp[8];
    __shared__ int sh_ne;
    __shared__ float ps[256];
    __shared__ float contrib[64];

    if (blockIdx.x == 64) {
        // ---- exp_counts + l_aux ----
        const int eidx = tid >> 2, q = tid & 3;
        float s = 0.f;
        for (int bkt = q * 256; bkt < q * 256 + 256; bkt++) s += g_cspart[bkt * 64 + eidx];
        ps[tid] = s;
        __syncthreads();
        if (tid < 64) {
            float me = (ps[tid * 4] + ps[tid * 4 + 1] + ps[tid * 4 + 2] + ps[tid * 4 + 3]) / (float)S;
            float ce = (float)g_counts[tid] / (float)S;
            contrib[tid] = me * ce * (float)E;
            out[1 + 2 * SEC + tid] = (float)g_counts[tid];
        }
        __syncthreads();
        if (tid == 0) {
            float l = 0.f;
            for (int i = 0; i < 64; i++) l += contrib[i];
            out[0] = l;
        }
        return;
    }

    const int e = blockIdx.x;

    // ---- pass 1: ordered compaction of (bits, token) for assigned tokens ----
    int base = 0;
    for (int c0 = 0; c0 < S; c0 += 256) {
        const int t = c0 + tid;
        const bool a = (g_assign[t] == e);
        unsigned b = 0u;
        if (a) b = __float_as_uint(noise[(size_t)t * E + e]);
        unsigned bal = __ballot_sync(0xFFFFFFFFu, a);
        if (lane == 0) red[wid] = __popc(bal);
        __syncthreads();
        int off = 0;
        for (int i = 0; i < wid; i++) off += red[i];
        int tot = 0;
#pragma unroll
        for (int i = 0; i < 8; i++) tot += red[i];
        if (a) {
            int pos = base + off + __popc(bal & ((1u << lane) - 1u));
            if (pos < K3_SMEM_CAP) {
                bits[pos] = b;
                tok[pos]  = (unsigned short)t;
            }
        }
        base += tot;
        __syncthreads();
    }
    if (tid == 0) sh_ne = base;
    __syncthreads();
    const int ne = sh_ne;
    const bool smem_ok = (ne <= K3_SMEM_CAP);

    // ---- pass 2: binary search for threshold T ----
    unsigned lo = 0u, hi = 0x3F7FFFFFu;
    while (lo < hi) {
        unsigned mid = lo + ((hi - lo + 1) >> 1);   // mid >= 1
        int c = 0;
        if (smem_ok) {
            for (int i = tid; i < ne; i += 256) c += (bits[i] >= mid);
        } else {
            for (int t = tid; t < S; t += 256)
                if (g_assign[t] == e)
                    c += (__float_as_uint(noise[(size_t)t * E + e]) >= mid);
        }
#pragma unroll
        for (int o = 16; o; o >>= 1) c += __shfl_xor_sync(0xFFFFFFFFu, c, o);
        if (lane == 0) red[wid] = c;
        __syncthreads();
        int tot = 0;
#pragma unroll
        for (int i = 0; i < 8; i++) tot += red[i];
        __syncthreads();
        if (tot >= CAP) lo = mid; else hi = mid - 1;
    }
    const unsigned T = lo;

    // ---- pass 3: count strictly-greater ----
    int kg;
    {
        int c = 0;
        const unsigned q = T + 1u;
        if (smem_ok) {
            for (int i = tid; i < ne; i += 256) c += (bits[i] >= q);
        } else {
            for (int t = tid; t < S; t += 256)
                if (g_assign[t] == e)
                    c += (__float_as_uint(noise[(size_t)t * E + e]) >= q);
        }
#pragma unroll
        for (int o = 16; o; o >>= 1) c += __shfl_xor_sync(0xFFFFFFFFu, c, o);
        if (lane == 0) red[wid] = c;
        __syncthreads();
        int tot = 0;
#pragma unroll
        for (int i = 0; i < 8; i++) tot += red[i];
        kg = tot;
        __syncthreads();
    }
    const int remaining = CAP - kg;

    if (smem_ok && T > 0u) {
        // ---- pass 4 (fast): ordered walk of compacted list in shared ----
        int kbase = 0, eqbase = 0;
        const int chunks = (ne + 255) >> 8;
        for (int ch = 0; ch < chunks; ch++) {
            const int i = ch * 256 + tid;
            const bool valid = (i < ne);
            unsigned v = valid ? bits[i] : 0u;
            const bool gt = valid && (v > T);
            const bool eq = valid && (v == T);

            unsigned beq = __ballot_sync(0xFFFFFFFFu, eq);
            if (lane == 0) weq[wid] = __popc(beq);
            __syncthreads();
            int eqoff = 0;
            for (int k = 0; k < wid; k++) eqoff += weq[k];
            int eqtot = 0;
#pragma unroll
            for (int k = 0; k < 8; k++) eqtot += weq[k];
            const int eqrank = eqbase + eqoff + __popc(beq & ((1u << lane) - 1u));

            const bool kept = gt || (eq && eqrank < remaining);
            unsigned bk = __ballot_sync(0xFFFFFFFFu, kept);
            if (lane == 0) wkp[wid] = __popc(bk);
            __syncthreads();
            int koff = 0;
            for (int k = 0; k < wid; k++) koff += wkp[k];
            int ktot = 0;
#pragma unroll
            for (int k = 0; k < 8; k++) ktot += wkp[k];

            if (kept) {
                const int slot = kbase + koff + __popc(bk & ((1u << lane) - 1u));
                const int t = tok[i];
                const long long off = ((long long)t * E + e) * (long long)CAP + slot;
                out[1 + off]       = g_topgate[t];   // combine_weights
                out[1 + SEC + off] = 1.0f;           // dispatch_mask
            }
            kbase  += ktot;
            eqbase += eqtot;
            __syncthreads();
        }
    } else {
        // ---- pass 4 (general): full global scan. Covers T==0 (zero-valued
        //      ties include unassigned tokens per top_k semantics) and
        //      the ne>cap fallback. ----
        int kbase = 0, eqbase = 0;
        for (int c0 = 0; c0 < S; c0 += 256) {
            const int t = c0 + tid;
            const bool a = (g_assign[t] == e);
            unsigned v = 0u;
            if (a) v = __float_as_uint(noise[(size_t)t * E + e]);
            const bool gt = a && (v > T);
            const bool eq = (v == T);   // for T==0 includes unassigned tokens

            unsigned beq = __ballot_sync(0xFFFFFFFFu, eq);
            if (lane == 0) weq[wid] = __popc(beq);
            __syncthreads();
            int eqoff = 0;
            for (int k = 0; k < wid; k++) eqoff += weq[k];
            int eqtot = 0;
#pragma unroll
            for (int k = 0; k < 8; k++) eqtot += weq[k];
            const int eqrank = eqbase + eqoff + __popc(beq & ((1u << lane) - 1u));

            const bool kept = a && (gt || (eq && eqrank < remaining));
            unsigned bk = __ballot_sync(0xFFFFFFFFu, kept);
            if (lane == 0) wkp[wid] = __popc(bk);
            __syncthreads();
            int koff = 0;
            for (int k = 0; k < wid; k++) koff += wkp[k];
            int ktot = 0;
#pragma unroll
            for (int k = 0; k < 8; k++) ktot += wkp[k];

            if (kept) {
                const int slot = kbase + koff + __popc(bk & ((1u << lane) - 1u));
                const long long off = ((long long)t * E + e) * (long long)CAP + slot;
                out[1 + off]       = g_topgate[t];
                out[1 + SEC + off] = 1.0f;
            }
            kbase  += ktot;
            eqbase += eqtot;
            __syncthreads();
        }
    }
}

// ==========================================================================
extern "C" void kernel_launch(void* const* d_in, const int* in_sizes, int n_in,
                              void* d_out, int out_size) {
    const float* x     = (const float*)d_in[0];
    const float* w     = (const float*)d_in[1];
    const float* noise = (const float*)d_in[2];
    float* out = (float*)d_out;
    const long long n = (long long)out_size;

    k1_fused<<<GEMM_BLOCKS, 128>>>(x, w, out, n);
    k2_gate<<<1024, 256>>>();
    k3_select<<<65, 256>>>(noise, out);
}